// round 1
// baseline (speedup 1.0000x reference)
#include <cuda_runtime.h>
#include <cstdint>

#define B_    4
#define C_    384
#define HW_   16384
#define NH_   8
#define HD_   48
#define OC3_  1152
#define NSPLIT 8

typedef unsigned long long u64;

// Scratch (device globals — no allocation allowed)
__device__ float g_qkv[(size_t)B_ * OC3_ * HW_];                 // 302 MB
__device__ float g_gram[(size_t)NSPLIT * B_ * NH_ * 96 * 96];    // partial Grams
__device__ float g_attn[(size_t)B_ * NH_ * HD_ * HD_];
__device__ float g_weff[(size_t)B_ * C_ * C_];

// ---- packed f32x2 helpers (Blackwell dual-rate fp32) ----
__device__ __forceinline__ u64 pk2(float lo, float hi) {
    u64 r; asm("mov.b64 %0, {%1,%2};" : "=l"(r) : "f"(lo), "f"(hi)); return r;
}
__device__ __forceinline__ void upk2(u64 v, float& lo, float& hi) {
    asm("mov.b64 {%0,%1}, %2;" : "=f"(lo), "=f"(hi) : "l"(v));
}
__device__ __forceinline__ u64 fma2(u64 a, u64 b, u64 c) {
    u64 d; asm("fma.rn.f32x2 %0, %1, %2, %3;" : "=l"(d) : "l"(a), "l"(b), "l"(c)); return d;
}

// ============================================================================
// Generic fp32 GEMM: C[b] = A[b] (MxK, row-major) * B[b] (KxN, row-major) + bias
// BM=BN=128, BK=16, 256 threads, 8x8 per thread via f32x2.
// Requires M%128==0, N%128==0, K%16==0 (true for all our shapes).
// ============================================================================
__global__ void __launch_bounds__(256, 2)
gemm_f32(const float* __restrict__ A, const float* __restrict__ Bm,
         float* __restrict__ Cm, int M, int N, int K,
         long long sA, long long sB, long long sC,
         const float* __restrict__ bias)
{
    const int BM = 128, BN = 128, BK = 16;
    __shared__ __align__(16) float As[BK][BM];
    __shared__ __align__(16) float Bs[BK][BN];

    int bz = blockIdx.z;
    A  += (size_t)bz * sA;
    Bm += (size_t)bz * sB;
    Cm += (size_t)bz * sC;
    const int tm = blockIdx.y * BM, tn = blockIdx.x * BN;
    const int tid = threadIdx.x;
    const int tx = tid & 15, ty = tid >> 4;

    u64 acc[8][4];
#pragma unroll
    for (int i = 0; i < 8; i++)
#pragma unroll
        for (int p = 0; p < 4; p++) acc[i][p] = 0ull;

    for (int k0 = 0; k0 < K; k0 += BK) {
        // A tile: 128 rows x 16 k  (store transposed As[k][m])
#pragma unroll
        for (int i = 0; i < 2; i++) {
            int f4 = tid + 256 * i;          // 0..511
            int r  = f4 >> 2;                // 0..127
            int c4 = (f4 & 3) << 2;          // 0,4,8,12
            float4 v = *reinterpret_cast<const float4*>(&A[(size_t)(tm + r) * K + k0 + c4]);
            As[c4 + 0][r] = v.x; As[c4 + 1][r] = v.y;
            As[c4 + 2][r] = v.z; As[c4 + 3][r] = v.w;
        }
        // B tile: 16 k x 128 n
#pragma unroll
        for (int i = 0; i < 2; i++) {
            int f4 = tid + 256 * i;
            int r  = f4 >> 5;                // 0..15
            int c4 = (f4 & 31) << 2;         // 0..124
            *reinterpret_cast<float4*>(&Bs[r][c4]) =
                *reinterpret_cast<const float4*>(&Bm[(size_t)(k0 + r) * N + tn + c4]);
        }
        __syncthreads();
#pragma unroll
        for (int kk = 0; kk < BK; kk++) {
            u64 av[8];
#pragma unroll
            for (int i = 0; i < 8; i++) { float a = As[kk][ty * 8 + i]; av[i] = pk2(a, a); }
            u64 bv[4];
            const u64* bp = reinterpret_cast<const u64*>(&Bs[kk][tx * 8]);
#pragma unroll
            for (int p = 0; p < 4; p++) bv[p] = bp[p];
#pragma unroll
            for (int i = 0; i < 8; i++)
#pragma unroll
                for (int p = 0; p < 4; p++)
                    acc[i][p] = fma2(av[i], bv[p], acc[i][p]);
        }
        __syncthreads();
    }

#pragma unroll
    for (int i = 0; i < 8; i++) {
        int row = tm + ty * 8 + i;
        float bval = bias ? bias[row] : 0.0f;
        float o[8];
#pragma unroll
        for (int p = 0; p < 4; p++) upk2(acc[i][p], o[2 * p], o[2 * p + 1]);
#pragma unroll
        for (int j = 0; j < 8; j++) o[j] += bval;
        float4* cp = reinterpret_cast<float4*>(&Cm[(size_t)row * N + tn + tx * 8]);
        cp[0] = make_float4(o[0], o[1], o[2], o[3]);
        cp[1] = make_float4(o[4], o[5], o[6], o[7]);
    }
}

// ============================================================================
// Gram kernel: per (b, head), G = Y Y^T, Y = [q; k] in R^{96 x 16384}.
// Split-K over NSPLIT splits (grid.x), partial results to g_gram.
// 256 threads, each computes 6x6 via f32x2 (6 rows x 3 col-pairs).
// ============================================================================
__global__ void __launch_bounds__(256, 2)
gram_kernel(int ksplit)
{
    const int BK = 32;
    __shared__ __align__(16) float Ys[BK][98];   // pad 98 -> 2-way store conflicts max

    const int split = blockIdx.x;
    const int bh = blockIdx.y;
    const int b = bh >> 3, h = bh & 7;
    const int tid = threadIdx.x;
    const int tx = tid & 15, ty = tid >> 4;
    const size_t base = (size_t)b * OC3_ * HW_;
    const int k0base = split * ksplit;

    u64 acc[6][3];
#pragma unroll
    for (int i = 0; i < 6; i++)
#pragma unroll
        for (int p = 0; p < 3; p++) acc[i][p] = 0ull;

    for (int kt = 0; kt < ksplit; kt += BK) {
        // load 96 rows x 32 cols (768 float4), store transposed
#pragma unroll
        for (int i = 0; i < 3; i++) {
            int f4 = tid + 256 * i;          // 0..767
            int r  = f4 >> 3;                // 0..95
            int c4 = (f4 & 7) << 2;          // 0..28
            int ch = (r < 48) ? (h * HD_ + r) : (C_ + h * HD_ + (r - 48));
            float4 v = *reinterpret_cast<const float4*>(
                &g_qkv[base + (size_t)ch * HW_ + k0base + kt + c4]);
            Ys[c4 + 0][r] = v.x; Ys[c4 + 1][r] = v.y;
            Ys[c4 + 2][r] = v.z; Ys[c4 + 3][r] = v.w;
        }
        __syncthreads();
#pragma unroll
        for (int kk = 0; kk < BK; kk++) {
            u64 av[6];
#pragma unroll
            for (int i = 0; i < 6; i++) { float a = Ys[kk][ty * 6 + i]; av[i] = pk2(a, a); }
            u64 bv[3];
            const u64* bp = reinterpret_cast<const u64*>(&Ys[kk][tx * 6]);
#pragma unroll
            for (int p = 0; p < 3; p++) bv[p] = bp[p];
#pragma unroll
            for (int i = 0; i < 6; i++)
#pragma unroll
                for (int p = 0; p < 3; p++)
                    acc[i][p] = fma2(av[i], bv[p], acc[i][p]);
        }
        __syncthreads();
    }

    float* gout = &g_gram[((size_t)split * (B_ * NH_) + bh) * 96 * 96];
#pragma unroll
    for (int i = 0; i < 6; i++) {
        int row = ty * 6 + i;
#pragma unroll
        for (int p = 0; p < 3; p++) {
            float lo, hi; upk2(acc[i][p], lo, hi);
            int col = tx * 6 + 2 * p;
            gout[row * 96 + col]     = lo;
            gout[row * 96 + col + 1] = hi;
        }
    }
}

// ============================================================================
// Attention: sum split-K partials, norms from Gram diagonal, softmax rows.
// One block per (b, head).
// ============================================================================
__global__ void __launch_bounds__(256)
attn_kernel(const float* __restrict__ temperature)
{
    __shared__ float sG[48][48];
    __shared__ float sInv[96];
    const int bh = blockIdx.x;
    const int h = bh & 7;
    const int tid = threadIdx.x;

    for (int idx = tid; idx < 48 * 48; idx += 256) {
        int d = idx / 48, e = idx % 48;
        float s = 0.0f;
#pragma unroll
        for (int sp = 0; sp < NSPLIT; sp++)
            s += g_gram[((size_t)sp * (B_ * NH_) + bh) * 96 * 96 + d * 96 + 48 + e];
        sG[d][e] = s;
    }
    if (tid < 96) {
        float ss = 0.0f;
#pragma unroll
        for (int sp = 0; sp < NSPLIT; sp++)
            ss += g_gram[((size_t)sp * (B_ * NH_) + bh) * 96 * 96 + tid * 96 + tid];
        float n = sqrtf(ss);
        sInv[tid] = 1.0f / fmaxf(n, 1e-12f);
    }
    __syncthreads();

    const float temp = temperature[h];
    if (tid < 48) {
        int d = tid;
        float l[48];
        float mx = -1e30f;
#pragma unroll
        for (int e = 0; e < 48; e++) {
            float v = sG[d][e] * sInv[d] * sInv[48 + e] * temp;
            l[e] = v;
            mx = fmaxf(mx, v);
        }
        float sum = 0.0f;
#pragma unroll
        for (int e = 0; e < 48; e++) { l[e] = expf(l[e] - mx); sum += l[e]; }
        float inv = 1.0f / sum;
#pragma unroll
        for (int e = 0; e < 48; e++)
            g_attn[((size_t)bh * 48 + d) * 48 + e] = l[e] * inv;
    }
}

// ============================================================================
// W_eff[b][o][h*48+e] = sum_d proj_w[o][h*48+d] * attn[b,h,d,e]
// Folds attn@v into the projection GEMM. One block per (b, head).
// ============================================================================
__global__ void __launch_bounds__(256)
weff_kernel(const float* __restrict__ proj_w)
{
    __shared__ float sA[48][48];
    const int bh = blockIdx.x;
    const int b = bh >> 3, h = bh & 7;
    const int tid = threadIdx.x;

    for (int idx = tid; idx < 48 * 48; idx += 256)
        sA[idx / 48][idx % 48] = g_attn[(size_t)bh * 48 * 48 + idx];
    __syncthreads();

    for (int idx = tid; idx < 384 * 48; idx += 256) {
        int o = idx / 48, e = idx % 48;
        float s = 0.0f;
#pragma unroll
        for (int d = 0; d < 48; d++)
            s += proj_w[(size_t)o * C_ + h * 48 + d] * sA[d][e];
        g_weff[((size_t)b * C_ + o) * C_ + h * 48 + e] = s;
    }
}

// ============================================================================
extern "C" void kernel_launch(void* const* d_in, const int* in_sizes, int n_in,
                              void* d_out, int out_size)
{
    const float* x           = (const float*)d_in[0];
    const float* qkv_w       = (const float*)d_in[1];
    const float* proj_w      = (const float*)d_in[2];
    const float* proj_b      = (const float*)d_in[3];
    const float* temperature = (const float*)d_in[4];
    float* out = (float*)d_out;

    void* p;
    cudaGetSymbolAddress(&p, g_qkv);  float* qkv  = (float*)p;
    cudaGetSymbolAddress(&p, g_weff); float* weff = (float*)p;

    // K1: qkv[b] = qkv_w (1152x384) @ x[b] (384x16384)
    gemm_f32<<<dim3(HW_ / 128, OC3_ / 128, B_), 256>>>(
        qkv_w, x, qkv,
        OC3_, HW_, C_,
        0LL, (long long)C_ * HW_, (long long)OC3_ * HW_,
        nullptr);

    // K2: split-K Gram of [q;k] per (b, head)
    gram_kernel<<<dim3(NSPLIT, B_ * NH_), 256>>>(HW_ / NSPLIT);

    // K3a: norms + softmax -> attn
    attn_kernel<<<B_ * NH_, 256>>>(temperature);

    // K3b: fold attn into projection weights
    weff_kernel<<<B_ * NH_, 256>>>(proj_w);

    // K4: out[b] = W_eff[b] (384x384) @ v[b] (384x16384) + proj_b
    gemm_f32<<<dim3(HW_ / 128, C_ / 128, B_), 256>>>(
        weff, qkv + (size_t)2 * C_ * HW_, out,
        C_, HW_, C_,
        (long long)C_ * C_, (long long)OC3_ * HW_, (long long)C_ * HW_,
        proj_b);
}

// round 4
// speedup vs baseline: 2.0555x; 2.0555x over previous
#include <cuda_runtime.h>
#include <cstdint>

#define B_    4
#define C_    384
#define HW_   16384
#define NH_   8
#define HD_   48
#define OC3_  1152
#define NSPLIT 8
#define KSPLIT_ (HW_ / NSPLIT)   // 2048

// ---------------------------------------------------------------------------
// Scratch (device globals — no allocation allowed)
// ---------------------------------------------------------------------------
__device__ float g_qkv[(size_t)B_ * OC3_ * HW_];                 // 302 MB
__device__ float g_gram[(size_t)NSPLIT * B_ * NH_ * 96 * 96];
__device__ float g_attn[(size_t)B_ * NH_ * HD_ * HD_];
__device__ float g_weff[(size_t)B_ * C_ * C_];

// ---------------------------------------------------------------------------
// Helpers (sm_100-safe: ldmatrix + mma.sync only, no tcgen05)
// ---------------------------------------------------------------------------
__device__ __forceinline__ uint32_t smem_u32(const void* p) {
    uint32_t a;
    asm("{ .reg .u64 t; cvta.to.shared.u64 t, %1; cvt.u32.u64 %0, t; }" : "=r"(a) : "l"(p));
    return a;
}

// fp32 pair -> bf16x2 hi (exact truncation) and bf16x2 lo (rounded residual)
__device__ __forceinline__ void split2(uint32_t& hi, uint32_t& lo, float f0, float f1) {
    uint32_t u0 = __float_as_uint(f0), u1 = __float_as_uint(f1);
    asm("prmt.b32 %0, %1, %2, 0x7632;" : "=r"(hi) : "r"(u0), "r"(u1));
    float h0 = __uint_as_float(u0 & 0xFFFF0000u);
    float h1 = __uint_as_float(u1 & 0xFFFF0000u);
    float l0 = f0 - h0, l1 = f1 - h1;
    asm("cvt.rn.bf16x2.f32 %0, %1, %2;" : "=r"(lo) : "f"(l1), "f"(l0));
}

__device__ __forceinline__ void ldsm4(uint32_t* r, uint32_t addr) {
    asm volatile("ldmatrix.sync.aligned.m8n8.x4.shared.b16 {%0,%1,%2,%3}, [%4];"
                 : "=r"(r[0]), "=r"(r[1]), "=r"(r[2]), "=r"(r[3]) : "r"(addr));
}
__device__ __forceinline__ void ldsm4t(uint32_t* r, uint32_t addr) {
    asm volatile("ldmatrix.sync.aligned.m8n8.x4.trans.shared.b16 {%0,%1,%2,%3}, [%4];"
                 : "=r"(r[0]), "=r"(r[1]), "=r"(r[2]), "=r"(r[3]) : "r"(addr));
}
__device__ __forceinline__ void ldsm2(uint32_t* r, uint32_t addr) {
    asm volatile("ldmatrix.sync.aligned.m8n8.x2.shared.b16 {%0,%1}, [%2];"
                 : "=r"(r[0]), "=r"(r[1]) : "r"(addr));
}

__device__ __forceinline__ void mma16816(float* d, const uint32_t* a, const uint32_t* b) {
    asm volatile(
        "mma.sync.aligned.m16n8k16.row.col.f32.bf16.bf16.f32 "
        "{%0,%1,%2,%3}, {%4,%5,%6,%7}, {%8,%9}, {%0,%1,%2,%3};"
        : "+f"(d[0]), "+f"(d[1]), "+f"(d[2]), "+f"(d[3])
        : "r"(a[0]), "r"(a[1]), "r"(a[2]), "r"(a[3]), "r"(b[0]), "r"(b[1]));
}

// ===========================================================================
// GEMM: C[b] = A[b] (MxK rm) * B[b] (KxN rm) + bias.  Tile 128x128, BK=32.
// 8 warps 2x4 (warp tile 64x32). SMEM per stage:
//   A hi/lo: [128][40] halves (pad 8)    B hi/lo: [32][136] halves (pad 8)
// Epilogue staged via smem fp32 [128][132].
// ===========================================================================
#define AH_OFF 0
#define AL_OFF 10240
#define BH_OFF 20480
#define BL_OFF 29184
#define STG_SZ 37888
#define GEMM_SMEM 75776   // 2 stages; >= 128*132*4 epilogue region

__global__ void __launch_bounds__(256, 1)
gemm_tc(const float* __restrict__ A, const float* __restrict__ Bm,
        float* __restrict__ Cm, int M, int N, int K,
        long long sA, long long sB, long long sC,
        const float* __restrict__ bias)
{
    extern __shared__ char smem[];
    const uint32_t sb = smem_u32(smem);
    const int tid = threadIdx.x;
    const int wid = tid >> 5, lane = tid & 31;

    A  += (size_t)blockIdx.z * sA;
    Bm += (size_t)blockIdx.z * sB;
    Cm += (size_t)blockIdx.z * sC;
    const int tm = blockIdx.x * 128, tn = blockIdx.y * 128;
    const int warp_m = (wid >> 2) * 64, warp_n = (wid & 3) * 32;

    float acc[4][4][4];
#pragma unroll
    for (int i = 0; i < 4; i++)
#pragma unroll
        for (int j = 0; j < 4; j++)
#pragma unroll
            for (int p = 0; p < 4; p++) acc[i][j][p] = 0.0f;

    float4 ra[4], rb[4];

    auto LDG = [&](int c) {
        const int k0 = c * 32;
#pragma unroll
        for (int i = 0; i < 4; i++) {
            int idx = tid + 256 * i, m = idx >> 3, k4 = (idx & 7) << 2;
            ra[i] = *reinterpret_cast<const float4*>(&A[(size_t)(tm + m) * K + k0 + k4]);
        }
#pragma unroll
        for (int i = 0; i < 4; i++) {
            int idx = tid + 256 * i, kr = idx >> 5, n4 = (idx & 31) << 2;
            rb[i] = *reinterpret_cast<const float4*>(&Bm[(size_t)(k0 + kr) * N + tn + n4]);
        }
    };
    auto STS = [&](int s) {
        char* base = smem + s * STG_SZ;
#pragma unroll
        for (int i = 0; i < 4; i++) {
            int idx = tid + 256 * i, m = idx >> 3, k4 = (idx & 7) << 2;
            uint32_t off = (uint32_t)(m * 40 + k4) << 1;
            uint32_t h, l;
            split2(h, l, ra[i].x, ra[i].y);
            *reinterpret_cast<uint32_t*>(base + AH_OFF + off)     = h;
            *reinterpret_cast<uint32_t*>(base + AL_OFF + off)     = l;
            split2(h, l, ra[i].z, ra[i].w);
            *reinterpret_cast<uint32_t*>(base + AH_OFF + off + 4) = h;
            *reinterpret_cast<uint32_t*>(base + AL_OFF + off + 4) = l;
        }
#pragma unroll
        for (int i = 0; i < 4; i++) {
            int idx = tid + 256 * i, kr = idx >> 5, n4 = (idx & 31) << 2;
            uint32_t off = (uint32_t)(kr * 136 + n4) << 1;
            uint32_t h, l;
            split2(h, l, rb[i].x, rb[i].y);
            *reinterpret_cast<uint32_t*>(base + BH_OFF + off)     = h;
            *reinterpret_cast<uint32_t*>(base + BL_OFF + off)     = l;
            split2(h, l, rb[i].z, rb[i].w);
            *reinterpret_cast<uint32_t*>(base + BH_OFF + off + 4) = h;
            *reinterpret_cast<uint32_t*>(base + BL_OFF + off + 4) = l;
        }
    };
    auto MMASTEP = [&](int s, int ks) {
        const uint32_t stg = sb + s * STG_SZ;
        uint32_t ah[4][4], al[4][4], bh[4][2], bl[4][2];
        // A frags: rows = warp_m + mf*16 + (lane&15); k halves = ks*16 + (lane>>4)*8
        const uint32_t arow = (uint32_t)(warp_m + (lane & 15));
        const uint32_t akoff = (uint32_t)(ks * 16 + ((lane >> 4) << 3));
#pragma unroll
        for (int mf = 0; mf < 4; mf++) {
            uint32_t ad = stg + AH_OFF + (((arow + mf * 16) * 40 + akoff) << 1);
            ldsm4(ah[mf], ad);
            ldsm4(al[mf], ad + (AL_OFF - AH_OFF));
        }
        // B frags (trans): k row = ks*16 + (lane&7) + ((lane>>3)&1)*8 ; n = warp_n + (lane>>4)*8
        {
            uint32_t krow = (uint32_t)(ks * 16 + (lane & 7) + (((lane >> 3) & 1) << 3));
            uint32_t ncol = (uint32_t)(warp_n + ((lane >> 4) << 3));
            uint32_t bd = stg + BH_OFF + ((krow * 136 + ncol) << 1);
            uint32_t r4[4];
            ldsm4t(r4, bd);
            bh[0][0] = r4[0]; bh[0][1] = r4[1]; bh[1][0] = r4[2]; bh[1][1] = r4[3];
            ldsm4t(r4, bd + 32);   // n +16 halves
            bh[2][0] = r4[0]; bh[2][1] = r4[1]; bh[3][0] = r4[2]; bh[3][1] = r4[3];
            uint32_t bdl = bd + (BL_OFF - BH_OFF);
            ldsm4t(r4, bdl);
            bl[0][0] = r4[0]; bl[0][1] = r4[1]; bl[1][0] = r4[2]; bl[1][1] = r4[3];
            ldsm4t(r4, bdl + 32);
            bl[2][0] = r4[0]; bl[2][1] = r4[1]; bl[3][0] = r4[2]; bl[3][1] = r4[3];
        }
#pragma unroll
        for (int mf = 0; mf < 4; mf++)
#pragma unroll
            for (int nf = 0; nf < 4; nf++) {
                mma16816(acc[mf][nf], ah[mf], bh[nf]);
                mma16816(acc[mf][nf], ah[mf], bl[nf]);
                mma16816(acc[mf][nf], al[mf], bh[nf]);
            }
    };

    LDG(0); STS(0);
    __syncthreads();
    const int NC = K >> 5;
    for (int c = 0; c < NC; c++) {
        const int s = c & 1;
        if (c + 1 < NC) LDG(c + 1);
        MMASTEP(s, 0);
        MMASTEP(s, 1);
        if (c + 1 < NC) STS(1 - s);
        __syncthreads();
    }

    // Epilogue: stage fp32 [128][132] in smem, then coalesced float4 writes.
    float* cs = reinterpret_cast<float*>(smem);
    const int g = lane >> 2, t2 = (lane & 3) * 2;
#pragma unroll
    for (int mf = 0; mf < 4; mf++)
#pragma unroll
        for (int nf = 0; nf < 4; nf++) {
            int r0 = warp_m + mf * 16 + g;
            int c0 = warp_n + nf * 8 + t2;
            cs[r0 * 132 + c0]           = acc[mf][nf][0];
            cs[r0 * 132 + c0 + 1]       = acc[mf][nf][1];
            cs[(r0 + 8) * 132 + c0]     = acc[mf][nf][2];
            cs[(r0 + 8) * 132 + c0 + 1] = acc[mf][nf][3];
        }
    __syncthreads();
    {
        const int r = tid >> 1, cb = (tid & 1) * 64;
        const float bval = bias ? bias[tm + r] : 0.0f;
        float* op = Cm + (size_t)(tm + r) * N + tn + cb;
        const float* ip = &cs[r * 132 + cb];
#pragma unroll
        for (int j = 0; j < 16; j++) {
            float4 v = make_float4(ip[4 * j] + bval, ip[4 * j + 1] + bval,
                                   ip[4 * j + 2] + bval, ip[4 * j + 3] + bval);
            reinterpret_cast<float4*>(op)[j] = v;
        }
    }
}

// ===========================================================================
// Gram: per (b, head, split), G_partial = Y Y^T, Y = [q;k] 96 x KSPLIT_.
// Same buffer is A and B (non-trans ldmatrix both). Tiles [96][72] halves.
// Warps 2x4: warp tile 48M x 24N (3x3 frags). BK=64 (4 ksteps), double buf.
// ===========================================================================
#define YH_OFF 0
#define YL_OFF 13824
#define GSTG_SZ 27648
#define GRAM_SMEM 55296

__global__ void __launch_bounds__(256, 1)
gram_tc()
{
    extern __shared__ char smem[];
    const uint32_t sb = smem_u32(smem);
    const int tid = threadIdx.x;
    const int wid = tid >> 5, lane = tid & 31;
    const int split = blockIdx.x;
    const int bh = blockIdx.y;
    const int b = bh >> 3, h = bh & 7;
    const size_t gbase = (size_t)b * OC3_ * HW_;
    const int kbase = split * KSPLIT_;
    const int warp_m = (wid >> 2) * 48, warp_n = (wid & 3) * 24;

    float acc[3][3][4];
#pragma unroll
    for (int i = 0; i < 3; i++)
#pragma unroll
        for (int j = 0; j < 3; j++)
#pragma unroll
            for (int p = 0; p < 4; p++) acc[i][j][p] = 0.0f;

    float4 ry[6];
    auto LDG = [&](int c) {
        const int k0 = kbase + c * 64;
#pragma unroll
        for (int i = 0; i < 6; i++) {
            int idx = tid + 256 * i, r = idx >> 4, c4 = (idx & 15) << 2;
            int ch = (r < 48) ? (h * HD_ + r) : (C_ + h * HD_ + (r - 48));
            ry[i] = *reinterpret_cast<const float4*>(&g_qkv[gbase + (size_t)ch * HW_ + k0 + c4]);
        }
    };
    auto STS = [&](int s) {
        char* base = smem + s * GSTG_SZ;
#pragma unroll
        for (int i = 0; i < 6; i++) {
            int idx = tid + 256 * i, r = idx >> 4, c4 = (idx & 15) << 2;
            uint32_t off = (uint32_t)(r * 72 + c4) << 1;
            uint32_t hh, ll;
            split2(hh, ll, ry[i].x, ry[i].y);
            *reinterpret_cast<uint32_t*>(base + YH_OFF + off)     = hh;
            *reinterpret_cast<uint32_t*>(base + YL_OFF + off)     = ll;
            split2(hh, ll, ry[i].z, ry[i].w);
            *reinterpret_cast<uint32_t*>(base + YH_OFF + off + 4) = hh;
            *reinterpret_cast<uint32_t*>(base + YL_OFF + off + 4) = ll;
        }
    };
    auto MMASTEP = [&](int s, int ks) {
        const uint32_t stg = sb + s * GSTG_SZ;
        uint32_t ah[3][4], al[3][4], bh[3][2], bl[3][2];
        const uint32_t koff = (uint32_t)(ks * 16 + ((lane >> 4) << 3));
#pragma unroll
        for (int mf = 0; mf < 3; mf++) {
            uint32_t ad = stg + YH_OFF + (((uint32_t)(warp_m + mf * 16 + (lane & 15)) * 72 + koff) << 1);
            ldsm4(ah[mf], ad);
            ldsm4(al[mf], ad + (YL_OFF - YH_OFF));
        }
        {
            uint32_t bd = stg + YH_OFF + (((uint32_t)(warp_n + (lane & 15)) * 72 + koff) << 1);
            uint32_t r4[4];
            ldsm4(r4, bd);
            bh[0][0] = r4[0]; bh[0][1] = r4[2]; bh[1][0] = r4[1]; bh[1][1] = r4[3];
            ldsm4(r4, bd + (YL_OFF - YH_OFF));
            bl[0][0] = r4[0]; bl[0][1] = r4[2]; bl[1][0] = r4[1]; bl[1][1] = r4[3];
            uint32_t k2 = (uint32_t)(ks * 16 + (((lane >> 3) & 1) << 3));
            uint32_t bd2 = stg + YH_OFF + (((uint32_t)(warp_n + 16 + (lane & 7)) * 72 + k2) << 1);
            uint32_t r2[2];
            ldsm2(r2, bd2);
            bh[2][0] = r2[0]; bh[2][1] = r2[1];
            ldsm2(r2, bd2 + (YL_OFF - YH_OFF));
            bl[2][0] = r2[0]; bl[2][1] = r2[1];
        }
#pragma unroll
        for (int mf = 0; mf < 3; mf++)
#pragma unroll
            for (int nf = 0; nf < 3; nf++) {
                mma16816(acc[mf][nf], ah[mf], bh[nf]);
                mma16816(acc[mf][nf], ah[mf], bl[nf]);
                mma16816(acc[mf][nf], al[mf], bh[nf]);
            }
    };

    LDG(0); STS(0);
    __syncthreads();
    const int NC = KSPLIT_ >> 6;   // 32
    for (int c = 0; c < NC; c++) {
        const int s = c & 1;
        if (c + 1 < NC) LDG(c + 1);
        MMASTEP(s, 0); MMASTEP(s, 1); MMASTEP(s, 2); MMASTEP(s, 3);
        if (c + 1 < NC) STS(1 - s);
        __syncthreads();
    }

    float* gout = g_gram + ((size_t)split * (B_ * NH_) + bh) * 96 * 96;
    const int g = lane >> 2, t2 = (lane & 3) * 2;
#pragma unroll
    for (int mf = 0; mf < 3; mf++)
#pragma unroll
        for (int nf = 0; nf < 3; nf++) {
            int r0 = warp_m + mf * 16 + g;
            int c0 = warp_n + nf * 8 + t2;
            gout[r0 * 96 + c0]           = acc[mf][nf][0];
            gout[r0 * 96 + c0 + 1]       = acc[mf][nf][1];
            gout[(r0 + 8) * 96 + c0]     = acc[mf][nf][2];
            gout[(r0 + 8) * 96 + c0 + 1] = acc[mf][nf][3];
        }
}

// ============================================================================
// Attention: sum split-K partials, norms from Gram diagonal, softmax rows.
// ============================================================================
__global__ void __launch_bounds__(256)
attn_kernel(const float* __restrict__ temperature)
{
    __shared__ float sG[48][48];
    __shared__ float sInv[96];
    const int bh = blockIdx.x;
    const int h = bh & 7;
    const int tid = threadIdx.x;

    for (int idx = tid; idx < 48 * 48; idx += 256) {
        int d = idx / 48, e = idx % 48;
        float s = 0.0f;
#pragma unroll
        for (int sp = 0; sp < NSPLIT; sp++)
            s += g_gram[((size_t)sp * (B_ * NH_) + bh) * 96 * 96 + d * 96 + 48 + e];
        sG[d][e] = s;
    }
    if (tid < 96) {
        float ss = 0.0f;
#pragma unroll
        for (int sp = 0; sp < NSPLIT; sp++)
            ss += g_gram[((size_t)sp * (B_ * NH_) + bh) * 96 * 96 + tid * 96 + tid];
        float n = sqrtf(ss);
        sInv[tid] = 1.0f / fmaxf(n, 1e-12f);
    }
    __syncthreads();

    const float temp = temperature[h];
    if (tid < 48) {
        int d = tid;
        float l[48];
        float mx = -1e30f;
#pragma unroll
        for (int e = 0; e < 48; e++) {
            float v = sG[d][e] * sInv[d] * sInv[48 + e] * temp;
            l[e] = v;
            mx = fmaxf(mx, v);
        }
        float sum = 0.0f;
#pragma unroll
        for (int e = 0; e < 48; e++) { l[e] = expf(l[e] - mx); sum += l[e]; }
        float inv = 1.0f / sum;
#pragma unroll
        for (int e = 0; e < 48; e++)
            g_attn[((size_t)bh * 48 + d) * 48 + e] = l[e] * inv;
    }
}

// ============================================================================
// W_eff[b][o][h*48+e] = sum_d proj_w[o][h*48+d] * attn[b,h,d,e]
// ============================================================================
__global__ void __launch_bounds__(256)
weff_kernel(const float* __restrict__ proj_w)
{
    __shared__ float sA[48][48];
    const int bh = blockIdx.x;
    const int b = bh >> 3, h = bh & 7;
    const int tid = threadIdx.x;

    for (int idx = tid; idx < 48 * 48; idx += 256)
        sA[idx / 48][idx % 48] = g_attn[(size_t)bh * 48 * 48 + idx];
    __syncthreads();

    for (int idx = tid; idx < 384 * 48; idx += 256) {
        int o = idx / 48, e = idx % 48;
        float s = 0.0f;
#pragma unroll
        for (int d = 0; d < 48; d++)
            s += proj_w[(size_t)o * C_ + h * 48 + d] * sA[d][e];
        g_weff[((size_t)b * C_ + o) * C_ + h * 48 + e] = s;
    }
}

// ============================================================================
extern "C" void kernel_launch(void* const* d_in, const int* in_sizes, int n_in,
                              void* d_out, int out_size)
{
    const float* x           = (const float*)d_in[0];
    const float* qkv_w       = (const float*)d_in[1];
    const float* proj_w      = (const float*)d_in[2];
    const float* proj_b      = (const float*)d_in[3];
    const float* temperature = (const float*)d_in[4];
    float* out = (float*)d_out;

    void* p;
    cudaGetSymbolAddress(&p, g_qkv);  float* qkv  = (float*)p;
    cudaGetSymbolAddress(&p, g_weff); float* weff = (float*)p;

    cudaFuncSetAttribute((const void*)gemm_tc,
                         cudaFuncAttributeMaxDynamicSharedMemorySize, GEMM_SMEM);
    cudaFuncSetAttribute((const void*)gram_tc,
                         cudaFuncAttributeMaxDynamicSharedMemorySize, GRAM_SMEM);

    // K1: qkv[b] = qkv_w (1152x384) @ x[b] (384x16384)
    gemm_tc<<<dim3(OC3_ / 128, HW_ / 128, B_), 256, GEMM_SMEM>>>(
        qkv_w, x, qkv,
        OC3_, HW_, C_,
        0LL, (long long)C_ * HW_, (long long)OC3_ * HW_,
        nullptr);

    // K2: split-K Gram of [q;k] per (b, head) on mma.sync
    gram_tc<<<dim3(NSPLIT, B_ * NH_), 256, GRAM_SMEM>>>();

    // K3a: norms + softmax -> attn
    attn_kernel<<<B_ * NH_, 256>>>(temperature);

    // K3b: fold attn into projection weights
    weff_kernel<<<B_ * NH_, 256>>>(proj_w);

    // K4: out[b] = W_eff[b] (384x384) @ v[b] (384x16384) + proj_b
    gemm_tc<<<dim3(C_ / 128, HW_ / 128, B_), 256, GEMM_SMEM>>>(
        weff, qkv + (size_t)2 * C_ * HW_, out,
        C_, HW_, C_,
        (long long)C_ * C_, (long long)OC3_ * HW_, (long long)C_ * HW_,
        proj_b);
}

// round 6
// speedup vs baseline: 2.0886x; 1.0161x over previous
#include <cuda_runtime.h>
#include <cstdint>

#define B_    4
#define C_    384
#define HW_   16384
#define NH_   8
#define HD_   48
#define OC3_  1152
#define NSPLIT 8
#define KSPLIT_ (HW_ / NSPLIT)   // 2048

// ---------------------------------------------------------------------------
// Scratch (device globals — no allocation allowed)
// ---------------------------------------------------------------------------
__device__ float g_qkv[(size_t)B_ * OC3_ * HW_];                 // 302 MB
__device__ float g_gram[(size_t)NSPLIT * B_ * NH_ * 96 * 96];
__device__ float g_weff[(size_t)B_ * C_ * C_];

// ---------------------------------------------------------------------------
// Helpers (sm_100-safe: ldmatrix + mma.sync only, no tcgen05)
// ---------------------------------------------------------------------------
__device__ __forceinline__ uint32_t smem_u32(const void* p) {
    uint32_t a;
    asm("{ .reg .u64 t; cvta.to.shared.u64 t, %1; cvt.u32.u64 %0, t; }" : "=r"(a) : "l"(p));
    return a;
}

// fp32 pair -> bf16x2 hi (exact truncation) and bf16x2 lo (rounded residual)
__device__ __forceinline__ void split2(uint32_t& hi, uint32_t& lo, float f0, float f1) {
    uint32_t u0 = __float_as_uint(f0), u1 = __float_as_uint(f1);
    asm("prmt.b32 %0, %1, %2, 0x7632;" : "=r"(hi) : "r"(u0), "r"(u1));
    float h0 = __uint_as_float(u0 & 0xFFFF0000u);
    float h1 = __uint_as_float(u1 & 0xFFFF0000u);
    float l0 = f0 - h0, l1 = f1 - h1;
    asm("cvt.rn.bf16x2.f32 %0, %1, %2;" : "=r"(lo) : "f"(l1), "f"(l0));
}

__device__ __forceinline__ void ldsm4(uint32_t* r, uint32_t addr) {
    asm volatile("ldmatrix.sync.aligned.m8n8.x4.shared.b16 {%0,%1,%2,%3}, [%4];"
                 : "=r"(r[0]), "=r"(r[1]), "=r"(r[2]), "=r"(r[3]) : "r"(addr));
}
__device__ __forceinline__ void ldsm4t(uint32_t* r, uint32_t addr) {
    asm volatile("ldmatrix.sync.aligned.m8n8.x4.trans.shared.b16 {%0,%1,%2,%3}, [%4];"
                 : "=r"(r[0]), "=r"(r[1]), "=r"(r[2]), "=r"(r[3]) : "r"(addr));
}
__device__ __forceinline__ void ldsm2(uint32_t* r, uint32_t addr) {
    asm volatile("ldmatrix.sync.aligned.m8n8.x2.shared.b16 {%0,%1}, [%2];"
                 : "=r"(r[0]), "=r"(r[1]) : "r"(addr));
}

__device__ __forceinline__ void mma16816(float* d, const uint32_t* a, const uint32_t* b) {
    asm volatile(
        "mma.sync.aligned.m16n8k16.row.col.f32.bf16.bf16.f32 "
        "{%0,%1,%2,%3}, {%4,%5,%6,%7}, {%8,%9}, {%0,%1,%2,%3};"
        : "+f"(d[0]), "+f"(d[1]), "+f"(d[2]), "+f"(d[3])
        : "r"(a[0]), "r"(a[1]), "r"(a[2]), "r"(a[3]), "r"(b[0]), "r"(b[1]));
}

// ===========================================================================
// GEMM: C[b] = A[b] (MxK rm) * B[b] (KxN rm) + bias.  Tile 128x256, BK=32.
// 8 warps 2x4 (warp tile 64x64). SMEM per stage:
//   A hi/lo: [128][40] halves    B hi/lo: [32][264] halves
// Epilogue staged via smem fp32 [128][260].
// Requires M%128==0, N%256==0, K%32==0.
// ===========================================================================
#define AH_OFF 0
#define AL_OFF 10240
#define BH_OFF 20480
#define BL_OFF 37376
#define STG_SZ 54272
#define GEMM_SMEM 133120   // >= max(2*STG_SZ=108544, 128*260*4=133120)

__global__ void __launch_bounds__(256, 1)
gemm_tc(const float* __restrict__ A, const float* __restrict__ Bm,
        float* __restrict__ Cm, int M, int N, int K,
        long long sA, long long sB, long long sC,
        const float* __restrict__ bias)
{
    extern __shared__ char smem[];
    const uint32_t sb = smem_u32(smem);
    const int tid = threadIdx.x;
    const int wid = tid >> 5, lane = tid & 31;

    A  += (size_t)blockIdx.z * sA;
    Bm += (size_t)blockIdx.z * sB;
    Cm += (size_t)blockIdx.z * sC;
    const int tm = blockIdx.x * 128, tn = blockIdx.y * 256;
    const int warp_m = (wid >> 2) * 64, warp_n = (wid & 3) * 64;

    float acc[4][8][4];
#pragma unroll
    for (int i = 0; i < 4; i++)
#pragma unroll
        for (int j = 0; j < 8; j++)
#pragma unroll
            for (int p = 0; p < 4; p++) acc[i][j][p] = 0.0f;

    float4 ra[4], rb[8];

    auto LDG = [&](int c) {
        const int k0 = c * 32;
#pragma unroll
        for (int i = 0; i < 4; i++) {
            int idx = tid + 256 * i, m = idx >> 3, k4 = (idx & 7) << 2;
            ra[i] = *reinterpret_cast<const float4*>(&A[(size_t)(tm + m) * K + k0 + k4]);
        }
#pragma unroll
        for (int i = 0; i < 8; i++) {
            int idx = tid + 256 * i, kr = idx >> 6, n4 = (idx & 63) << 2;
            rb[i] = *reinterpret_cast<const float4*>(&Bm[(size_t)(k0 + kr) * N + tn + n4]);
        }
    };
    auto STS = [&](int s) {
        char* base = smem + s * STG_SZ;
#pragma unroll
        for (int i = 0; i < 4; i++) {
            int idx = tid + 256 * i, m = idx >> 3, k4 = (idx & 7) << 2;
            uint32_t off = (uint32_t)(m * 40 + k4) << 1;
            uint32_t h, l;
            split2(h, l, ra[i].x, ra[i].y);
            *reinterpret_cast<uint32_t*>(base + AH_OFF + off)     = h;
            *reinterpret_cast<uint32_t*>(base + AL_OFF + off)     = l;
            split2(h, l, ra[i].z, ra[i].w);
            *reinterpret_cast<uint32_t*>(base + AH_OFF + off + 4) = h;
            *reinterpret_cast<uint32_t*>(base + AL_OFF + off + 4) = l;
        }
#pragma unroll
        for (int i = 0; i < 8; i++) {
            int idx = tid + 256 * i, kr = idx >> 6, n4 = (idx & 63) << 2;
            uint32_t off = (uint32_t)(kr * 264 + n4) << 1;
            uint32_t h, l;
            split2(h, l, rb[i].x, rb[i].y);
            *reinterpret_cast<uint32_t*>(base + BH_OFF + off)     = h;
            *reinterpret_cast<uint32_t*>(base + BL_OFF + off)     = l;
            split2(h, l, rb[i].z, rb[i].w);
            *reinterpret_cast<uint32_t*>(base + BH_OFF + off + 4) = h;
            *reinterpret_cast<uint32_t*>(base + BL_OFF + off + 4) = l;
        }
    };
    auto MMASTEP = [&](int s, int ks) {
        const uint32_t stg = sb + s * STG_SZ;
        uint32_t bh[8][2], bl[8][2];
        // B frags (trans): k row = ks*16 + (lane&7) + ((lane>>3)&1)*8 ; n = warp_n + (lane>>4)*8
        {
            uint32_t krow = (uint32_t)(ks * 16 + (lane & 7) + (((lane >> 3) & 1) << 3));
            uint32_t ncol = (uint32_t)(warp_n + ((lane >> 4) << 3));
            uint32_t bd  = stg + BH_OFF + ((krow * 264 + ncol) << 1);
            uint32_t bdl = bd + (BL_OFF - BH_OFF);
            uint32_t r4[4];
#pragma unroll
            for (int j = 0; j < 4; j++) {   // n offsets 0,16,32,48
                ldsm4t(r4, bd + j * 32);
                bh[2 * j][0] = r4[0]; bh[2 * j][1] = r4[1];
                bh[2 * j + 1][0] = r4[2]; bh[2 * j + 1][1] = r4[3];
            }
#pragma unroll
            for (int j = 0; j < 4; j++) {
                ldsm4t(r4, bdl + j * 32);
                bl[2 * j][0] = r4[0]; bl[2 * j][1] = r4[1];
                bl[2 * j + 1][0] = r4[2]; bl[2 * j + 1][1] = r4[3];
            }
        }
        const uint32_t arow = (uint32_t)(warp_m + (lane & 15));
        const uint32_t akoff = (uint32_t)(ks * 16 + ((lane >> 4) << 3));
#pragma unroll
        for (int mf = 0; mf < 4; mf++) {
            uint32_t ah[4], al[4];
            uint32_t ad = stg + AH_OFF + (((arow + mf * 16) * 40 + akoff) << 1);
            ldsm4(ah, ad);
            ldsm4(al, ad + (AL_OFF - AH_OFF));
#pragma unroll
            for (int nf = 0; nf < 8; nf++) {
                mma16816(acc[mf][nf], ah, bh[nf]);
                mma16816(acc[mf][nf], ah, bl[nf]);
                mma16816(acc[mf][nf], al, bh[nf]);
            }
        }
    };

    LDG(0); STS(0);
    __syncthreads();
    const int NC = K >> 5;
    for (int c = 0; c < NC; c++) {
        const int s = c & 1;
        if (c + 1 < NC) LDG(c + 1);
        MMASTEP(s, 0);
        MMASTEP(s, 1);
        if (c + 1 < NC) STS(1 - s);
        __syncthreads();
    }

    // Epilogue: stage fp32 [128][260] in smem, then coalesced float4 writes.
    float* cs = reinterpret_cast<float*>(smem);
    const int g = lane >> 2, t2 = (lane & 3) * 2;
#pragma unroll
    for (int mf = 0; mf < 4; mf++)
#pragma unroll
        for (int nf = 0; nf < 8; nf++) {
            int r0 = warp_m + mf * 16 + g;
            int c0 = warp_n + nf * 8 + t2;
            cs[r0 * 260 + c0]           = acc[mf][nf][0];
            cs[r0 * 260 + c0 + 1]       = acc[mf][nf][1];
            cs[(r0 + 8) * 260 + c0]     = acc[mf][nf][2];
            cs[(r0 + 8) * 260 + c0 + 1] = acc[mf][nf][3];
        }
    __syncthreads();
    {
        const int r = tid >> 1, cb = (tid & 1) * 128;
        const float bval = bias ? bias[tm + r] : 0.0f;
        float* op = Cm + (size_t)(tm + r) * N + tn + cb;
        const float* ip = &cs[r * 260 + cb];
#pragma unroll
        for (int j = 0; j < 32; j++) {
            float4 v = make_float4(ip[4 * j] + bval, ip[4 * j + 1] + bval,
                                   ip[4 * j + 2] + bval, ip[4 * j + 3] + bval);
            reinterpret_cast<float4*>(op)[j] = v;
        }
    }
}

// ===========================================================================
// Gram: per (b, head, split), G_partial = Y Y^T, Y = [q;k] 96 x KSPLIT_.
// Same buffer is A and B (non-trans ldmatrix both). Tiles [96][72] halves.
// Warps 2x4: warp tile 48M x 24N (3x3 frags). BK=64 (4 ksteps), double buf.
// ===========================================================================
#define YH_OFF 0
#define YL_OFF 13824
#define GSTG_SZ 27648
#define GRAM_SMEM 55296

__global__ void __launch_bounds__(256, 1)
gram_tc()
{
    extern __shared__ char smem[];
    const uint32_t sb = smem_u32(smem);
    const int tid = threadIdx.x;
    const int wid = tid >> 5, lane = tid & 31;
    const int split = blockIdx.x;
    const int bh = blockIdx.y;
    const int b = bh >> 3, h = bh & 7;
    const size_t gbase = (size_t)b * OC3_ * HW_;
    const int kbase = split * KSPLIT_;
    const int warp_m = (wid >> 2) * 48, warp_n = (wid & 3) * 24;

    float acc[3][3][4];
#pragma unroll
    for (int i = 0; i < 3; i++)
#pragma unroll
        for (int j = 0; j < 3; j++)
#pragma unroll
            for (int p = 0; p < 4; p++) acc[i][j][p] = 0.0f;

    float4 ry[6];
    auto LDG = [&](int c) {
        const int k0 = kbase + c * 64;
#pragma unroll
        for (int i = 0; i < 6; i++) {
            int idx = tid + 256 * i, r = idx >> 4, c4 = (idx & 15) << 2;
            int ch = (r < 48) ? (h * HD_ + r) : (C_ + h * HD_ + (r - 48));
            ry[i] = *reinterpret_cast<const float4*>(&g_qkv[gbase + (size_t)ch * HW_ + k0 + c4]);
        }
    };
    auto STS = [&](int s) {
        char* base = smem + s * GSTG_SZ;
#pragma unroll
        for (int i = 0; i < 6; i++) {
            int idx = tid + 256 * i, r = idx >> 4, c4 = (idx & 15) << 2;
            uint32_t off = (uint32_t)(r * 72 + c4) << 1;
            uint32_t hh, ll;
            split2(hh, ll, ry[i].x, ry[i].y);
            *reinterpret_cast<uint32_t*>(base + YH_OFF + off)     = hh;
            *reinterpret_cast<uint32_t*>(base + YL_OFF + off)     = ll;
            split2(hh, ll, ry[i].z, ry[i].w);
            *reinterpret_cast<uint32_t*>(base + YH_OFF + off + 4) = hh;
            *reinterpret_cast<uint32_t*>(base + YL_OFF + off + 4) = ll;
        }
    };
    auto MMASTEP = [&](int s, int ks) {
        const uint32_t stg = sb + s * GSTG_SZ;
        uint32_t ah[3][4], al[3][4], bh[3][2], bl[3][2];
        const uint32_t koff = (uint32_t)(ks * 16 + ((lane >> 4) << 3));
#pragma unroll
        for (int mf = 0; mf < 3; mf++) {
            uint32_t ad = stg + YH_OFF + (((uint32_t)(warp_m + mf * 16 + (lane & 15)) * 72 + koff) << 1);
            ldsm4(ah[mf], ad);
            ldsm4(al[mf], ad + (YL_OFF - YH_OFF));
        }
        {
            uint32_t bd = stg + YH_OFF + (((uint32_t)(warp_n + (lane & 15)) * 72 + koff) << 1);
            uint32_t r4[4];
            ldsm4(r4, bd);
            bh[0][0] = r4[0]; bh[0][1] = r4[2]; bh[1][0] = r4[1]; bh[1][1] = r4[3];
            ldsm4(r4, bd + (YL_OFF - YH_OFF));
            bl[0][0] = r4[0]; bl[0][1] = r4[2]; bl[1][0] = r4[1]; bl[1][1] = r4[3];
            uint32_t k2 = (uint32_t)(ks * 16 + (((lane >> 3) & 1) << 3));
            uint32_t bd2 = stg + YH_OFF + (((uint32_t)(warp_n + 16 + (lane & 7)) * 72 + k2) << 1);
            uint32_t r2[2];
            ldsm2(r2, bd2);
            bh[2][0] = r2[0]; bh[2][1] = r2[1];
            ldsm2(r2, bd2 + (YL_OFF - YH_OFF));
            bl[2][0] = r2[0]; bl[2][1] = r2[1];
        }
#pragma unroll
        for (int mf = 0; mf < 3; mf++)
#pragma unroll
            for (int nf = 0; nf < 3; nf++) {
                mma16816(acc[mf][nf], ah[mf], bh[nf]);
                mma16816(acc[mf][nf], ah[mf], bl[nf]);
                mma16816(acc[mf][nf], al[mf], bh[nf]);
            }
    };

    LDG(0); STS(0);
    __syncthreads();
    const int NC = KSPLIT_ >> 6;   // 32
    for (int c = 0; c < NC; c++) {
        const int s = c & 1;
        if (c + 1 < NC) LDG(c + 1);
        MMASTEP(s, 0); MMASTEP(s, 1); MMASTEP(s, 2); MMASTEP(s, 3);
        if (c + 1 < NC) STS(1 - s);
        __syncthreads();
    }

    float* gout = g_gram + ((size_t)split * (B_ * NH_) + bh) * 96 * 96;
    const int g = lane >> 2, t2 = (lane & 3) * 2;
#pragma unroll
    for (int mf = 0; mf < 3; mf++)
#pragma unroll
        for (int nf = 0; nf < 3; nf++) {
            int r0 = warp_m + mf * 16 + g;
            int c0 = warp_n + nf * 8 + t2;
            gout[r0 * 96 + c0]           = acc[mf][nf][0];
            gout[r0 * 96 + c0 + 1]       = acc[mf][nf][1];
            gout[(r0 + 8) * 96 + c0]     = acc[mf][nf][2];
            gout[(r0 + 8) * 96 + c0 + 1] = acc[mf][nf][3];
        }
}

// ============================================================================
// Fused attention + W_eff: per (b, head) block.
//  1) reduce split-K Gram partials -> logits block + inv-norms
//  2) softmax rows -> sAttn (smem only)
//  3) W_eff[b][o][h*48+e] = sum_d proj_w[o][h*48+d] * sAttn[d][e]
// SMEM: sG 48x48 | sInv 96 | sAttn 48x48 | spw 384x49 (pad -> conflict-free)
// ============================================================================
#define AW_SG   0
#define AW_SINV 2304
#define AW_SATT 2400
#define AW_SPW  4704
#define AW_SMEM ((AW_SPW + 384 * 49) * 4)   // 94080 bytes

__global__ void __launch_bounds__(256)
attn_weff_kernel(const float* __restrict__ temperature,
                 const float* __restrict__ proj_w)
{
    extern __shared__ float sm[];
    float* sG    = sm + AW_SG;
    float* sInv  = sm + AW_SINV;
    float* sAttn = sm + AW_SATT;
    float* spw   = sm + AW_SPW;

    const int bh = blockIdx.x;
    const int b = bh >> 3, h = bh & 7;
    const int tid = threadIdx.x;

    // Gram reduction: q·k^T block
    for (int idx = tid; idx < 48 * 48; idx += 256) {
        int d = idx / 48, e = idx % 48;
        float s = 0.0f;
#pragma unroll
        for (int sp = 0; sp < NSPLIT; sp++)
            s += g_gram[((size_t)sp * (B_ * NH_) + bh) * 96 * 96 + d * 96 + 48 + e];
        sG[idx] = s;
    }
    if (tid < 96) {
        float ss = 0.0f;
#pragma unroll
        for (int sp = 0; sp < NSPLIT; sp++)
            ss += g_gram[((size_t)sp * (B_ * NH_) + bh) * 96 * 96 + tid * 96 + tid];
        sInv[tid] = 1.0f / fmaxf(sqrtf(ss), 1e-12f);
    }
    // Load proj_w slice: [384][48] -> spw stride 49
    for (int idx = tid; idx < 384 * 12; idx += 256) {
        int o = idx / 12, d4 = (idx % 12) * 4;
        float4 v = *reinterpret_cast<const float4*>(&proj_w[(size_t)o * C_ + h * 48 + d4]);
        float* dst = &spw[o * 49 + d4];
        dst[0] = v.x; dst[1] = v.y; dst[2] = v.z; dst[3] = v.w;
    }
    __syncthreads();

    // Softmax rows
    const float temp = temperature[h];
    if (tid < 48) {
        int d = tid;
        float l[48];
        float mx = -1e30f;
#pragma unroll
        for (int e = 0; e < 48; e++) {
            float v = sG[d * 48 + e] * sInv[d] * sInv[48 + e] * temp;
            l[e] = v;
            mx = fmaxf(mx, v);
        }
        float sum = 0.0f;
#pragma unroll
        for (int e = 0; e < 48; e++) { l[e] = expf(l[e] - mx); sum += l[e]; }
        float inv = 1.0f / sum;
#pragma unroll
        for (int e = 0; e < 48; e++) sAttn[d * 48 + e] = l[e] * inv;
    }
    __syncthreads();

    // W_eff: each thread handles o = tid, tid+256
    for (int o = tid; o < 384; o += 256) {
        const float* pw = &spw[o * 49];
        float* wout = &g_weff[((size_t)b * C_ + o) * C_ + h * 48];
#pragma unroll
        for (int eb = 0; eb < 6; eb++) {
            float a0 = 0, a1 = 0, a2 = 0, a3 = 0, a4 = 0, a5 = 0, a6 = 0, a7 = 0;
#pragma unroll 8
            for (int d = 0; d < 48; d++) {
                float p = pw[d];
                const float* ar = &sAttn[d * 48 + eb * 8];
                a0 += p * ar[0]; a1 += p * ar[1]; a2 += p * ar[2]; a3 += p * ar[3];
                a4 += p * ar[4]; a5 += p * ar[5]; a6 += p * ar[6]; a7 += p * ar[7];
            }
            wout[eb * 8 + 0] = a0; wout[eb * 8 + 1] = a1;
            wout[eb * 8 + 2] = a2; wout[eb * 8 + 3] = a3;
            wout[eb * 8 + 4] = a4; wout[eb * 8 + 5] = a5;
            wout[eb * 8 + 6] = a6; wout[eb * 8 + 7] = a7;
        }
    }
}

// ============================================================================
extern "C" void kernel_launch(void* const* d_in, const int* in_sizes, int n_in,
                              void* d_out, int out_size)
{
    const float* x           = (const float*)d_in[0];
    const float* qkv_w       = (const float*)d_in[1];
    const float* proj_w      = (const float*)d_in[2];
    const float* proj_b      = (const float*)d_in[3];
    const float* temperature = (const float*)d_in[4];
    float* out = (float*)d_out;

    void* p;
    cudaGetSymbolAddress(&p, g_qkv);  float* qkv  = (float*)p;
    cudaGetSymbolAddress(&p, g_weff); float* weff = (float*)p;

    cudaFuncSetAttribute((const void*)gemm_tc,
                         cudaFuncAttributeMaxDynamicSharedMemorySize, GEMM_SMEM);
    cudaFuncSetAttribute((const void*)gram_tc,
                         cudaFuncAttributeMaxDynamicSharedMemorySize, GRAM_SMEM);
    cudaFuncSetAttribute((const void*)attn_weff_kernel,
                         cudaFuncAttributeMaxDynamicSharedMemorySize, AW_SMEM);

    // K1: qkv[b] = qkv_w (1152x384) @ x[b] (384x16384)
    gemm_tc<<<dim3(OC3_ / 128, HW_ / 256, B_), 256, GEMM_SMEM>>>(
        qkv_w, x, qkv,
        OC3_, HW_, C_,
        0LL, (long long)C_ * HW_, (long long)OC3_ * HW_,
        nullptr);

    // K2: split-K Gram of [q;k] per (b, head) on mma.sync
    gram_tc<<<dim3(NSPLIT, B_ * NH_), 256, GRAM_SMEM>>>();

    // K3: fused norms + softmax + attn-fold into projection weights
    attn_weff_kernel<<<B_ * NH_, 256, AW_SMEM>>>(temperature, proj_w);

    // K4: out[b] = W_eff[b] (384x384) @ v[b] (384x16384) + proj_b
    gemm_tc<<<dim3(C_ / 128, HW_ / 256, B_), 256, GEMM_SMEM>>>(
        weff, qkv + (size_t)2 * C_ * HW_, out,
        C_, HW_, C_,
        (long long)C_ * C_, (long long)OC3_ * HW_, (long long)C_ * HW_,
        proj_b);
}